// round 17
// baseline (speedup 1.0000x reference)
#include <cuda_runtime.h>
#include <cuda_fp16.h>
#include <math.h>
#include <stdint.h>

// Problem constants
constexpr int B_  = 4;
constexpr int T_  = 2048;
constexpr int C_  = 1024;
constexpr int H_  = 16;
constexpr int HD_ = 64;
constexpr int M_  = B_ * T_;   // 8192 rows

// Scratch (device globals: allocation-free rule)
__device__ __half g_xh[(size_t)M_ * C_];        // 16 MB  x (half)
__device__ __half g_wah[(size_t)3 * C_ * C_];   // 6 MB   w_attn^T [N=3072][K=1024]
__device__ __half g_wph[(size_t)C_ * C_];       // 2 MB   w_proj^T [N=1024][K=1024]
__device__ __half g_qkh[(size_t)M_ * 2 * C_];   // 32 MB  Q(scaled)+K  [tok][2048]
__device__ __half g_vt[(size_t)B_ * H_ * HD_ * T_]; // 16 MB V^T [b*16+h][d][tok]
__device__ __half g_yh[(size_t)M_ * C_];        // 16 MB  attention out (half)

// Q pre-scale: (1/sqrt(64)) * log2(e)  -> softmax uses bare ex2
#define QSCALE 0.180336880f

// ---------------------------------------------------------------------------
// helpers
// ---------------------------------------------------------------------------
__device__ __forceinline__ void mma_f16(float* c, const uint32_t* a, const uint32_t* b) {
    asm volatile(
        "mma.sync.aligned.m16n8k16.row.col.f32.f16.f16.f32 "
        "{%0,%1,%2,%3},{%4,%5,%6,%7},{%8,%9},{%0,%1,%2,%3};"
        : "+f"(c[0]), "+f"(c[1]), "+f"(c[2]), "+f"(c[3])
        : "r"(a[0]), "r"(a[1]), "r"(a[2]), "r"(a[3]), "r"(b[0]), "r"(b[1]));
}

#define LDSM_X4(r0, r1, r2, r3, addr) \
    asm volatile("ldmatrix.sync.aligned.m8n8.x4.shared.b16 {%0,%1,%2,%3}, [%4];" \
                 : "=r"(r0), "=r"(r1), "=r"(r2), "=r"(r3) : "r"(addr))

#define CP_ASYNC16(s, g) \
    asm volatile("cp.async.cg.shared.global [%0], [%1], 16;" :: "r"(s), "l"(g))
#define CP_COMMIT() asm volatile("cp.async.commit_group;")
#define CP_WAIT0()  asm volatile("cp.async.wait_group 0;")

__device__ __forceinline__ uint32_t smem_u32(const void* p) {
    return (uint32_t)__cvta_generic_to_shared(p);
}
__device__ __forceinline__ uint32_t h2u(__half2 h) {
    return *reinterpret_cast<uint32_t*>(&h);
}
__device__ __forceinline__ float ex2f(float x) {
    float r;
    asm("ex2.approx.ftz.f32 %0, %1;" : "=f"(r) : "f"(x));
    return r;
}

// fp32 -> fp16 elementwise (n4 = quarters)
__global__ void cvt_f2h_kernel(const float* __restrict__ in, __half* __restrict__ out, int n4) {
    int i = blockIdx.x * blockDim.x + threadIdx.x;
    if (i < n4) {
        float4 v = ((const float4*)in)[i];
        uint2 u;
        u.x = h2u(__floats2half2_rn(v.x, v.y));
        u.y = h2u(__floats2half2_rn(v.z, v.w));
        ((uint2*)out)[i] = u;
    }
}

// transpose + fp16: in[K][N] fp32 -> out[N][K] half
__global__ __launch_bounds__(256)
void transpose_f2h_kernel(const float* __restrict__ in, __half* __restrict__ out,
                          int K, int N) {
    __shared__ float t[32][33];
    const int k0 = blockIdx.y * 32, n0 = blockIdx.x * 32;
    const int x = threadIdx.x, y0 = threadIdx.y;
    for (int i = y0; i < 32; i += 8)
        t[i][x] = in[(size_t)(k0 + i) * N + n0 + x];
    __syncthreads();
    for (int i = y0; i < 32; i += 8)
        out[(size_t)(n0 + i) * K + k0 + x] = __float2half_rn(t[x][i]);
}

// ---------------------------------------------------------------------------
// PERSISTENT fp16 mma.sync GEMM with ldmatrix fragments.
// CTA 128x128, 256 threads, warp tile 64x32, BK=32, 4-stage ring, 2 CTAs/SM.
// grid = 296 (exactly 2/SM): each CTA loops tiles with stride gridDim.x
// (kills the 5.19-wave quantization of the non-persistent launch).
// MODE 1: Q (xQSCALE) + K -> g_qkh [tok][2048], V -> g_vt transposed.
// MODE 0: proj output -> fp32 C [M][1024].
// ---------------------------------------------------------------------------
constexpr int HBK = 32;
constexpr int HSTR = 40;
constexpr int A_H = 128 * HSTR;         // 5120 halves (10240 B)
constexpr int STG_B = 2 * A_H * 2;      // 20480 B per stage
constexpr int HG_SMEM = 4 * STG_B;      // 81920 B
constexpr int PGRID = 296;              // 148 SMs x 2 CTAs

template <int MODE, int NX, int NTOT>
__global__ __launch_bounds__(256, 2)
void hgemm(const __half* __restrict__ A, const __half* __restrict__ Bt,
           void* __restrict__ Cout) {
    extern __shared__ __half hs[];
    const uint32_t sb0 = smem_u32(hs);

    const int tid = threadIdx.x;
    const int w = tid >> 5, lane = tid & 31;
    const int g = lane >> 2, t = lane & 3;
    const int lrow = lane & 7, lmat = lane >> 3;
    const int wm = (w >> 2) * 64;
    const int wn = (w & 3) * 32;
    const int kkst = w & 1;

    const uint32_t aoff = (uint32_t)(((((lmat & 1) * 8) + lrow) * HSTR + (lmat >> 1) * 8) * 2);
    const uint32_t boff = (uint32_t)(((((lmat >> 1) * 8) + lrow) * HSTR + (lmat & 1) * 8) * 2);

    const int ar = tid >> 2, ac = tid & 3;
    const uint32_t a0_off = (uint32_t)(ar * 80 + ac * 16);
    const uint32_t a1_off = a0_off + 64 * 80;
    const uint32_t b0_off = (uint32_t)(10240 + ar * 80 + ac * 16);
    const uint32_t b1_off = b0_off + 64 * 80;

    for (int tile = blockIdx.x; tile < NTOT; tile += PGRID) {
        const int bx = tile % NX, by = tile / NX;
        const int brow = by * 128;
        const int bcol = bx * 128;

        const __half* Ag0 = A  + (size_t)(brow + ar) * C_ + ac * 8;
        const __half* Ag1 = Ag0 + (size_t)64 * C_;
        const __half* Bg0 = Bt + (size_t)(bcol + ar) * C_ + ac * 8;
        const __half* Bg1 = Bg0 + (size_t)64 * C_;

        auto issue = [&](int kt, int buf) {
            const uint32_t sb = sb0 + buf * STG_B;
            CP_ASYNC16(sb + a0_off, Ag0 + kt * HBK);
            CP_ASYNC16(sb + a1_off, Ag1 + kt * HBK);
            CP_ASYNC16(sb + b0_off, Bg0 + kt * HBK);
            CP_ASYNC16(sb + b1_off, Bg1 + kt * HBK);
        };

        float acc[4][4][4];
#pragma unroll
        for (int mt = 0; mt < 4; mt++)
#pragma unroll
            for (int nt = 0; nt < 4; nt++)
#pragma unroll
                for (int c = 0; c < 4; c++) acc[mt][nt][c] = 0.f;

        issue(0, 0); CP_COMMIT();
        issue(1, 1); CP_COMMIT();
        issue(2, 2); CP_COMMIT();

        constexpr int NK = C_ / HBK;
        for (int kt = 0; kt < NK; kt++) {
            asm volatile("cp.async.wait_group 2;");
            __syncthreads();
            if (kt + 3 < NK) issue(kt + 3, (kt + 3) & 3);
            CP_COMMIT();

            const uint32_t as_u = sb0 + (kt & 3) * STG_B;
            const uint32_t bs_u = as_u + 10240;
#pragma unroll
            for (int kk = 0; kk < 2; kk++) {
                const int kkk = kk ^ kkst;
                const uint32_t koff = kkk * 32;
                uint32_t af[4][4], bf[4][2];
#pragma unroll
                for (int mt = 0; mt < 4; mt++)
                    LDSM_X4(af[mt][0], af[mt][1], af[mt][2], af[mt][3],
                            as_u + (uint32_t)((wm + mt * 16) * (HSTR * 2)) + koff + aoff);
#pragma unroll
                for (int np = 0; np < 2; np++)
                    LDSM_X4(bf[2 * np][0], bf[2 * np][1], bf[2 * np + 1][0], bf[2 * np + 1][1],
                            bs_u + (uint32_t)((wn + np * 16) * (HSTR * 2)) + koff + boff);
#pragma unroll
                for (int mt = 0; mt < 4; mt++)
#pragma unroll
                    for (int nt = 0; nt < 4; nt++)
                        mma_f16(acc[mt][nt], af[mt], bf[nt]);
            }
        }

        // ---- epilogue ----
        if (MODE == 0) {
            float* Cf = (float*)Cout;
#pragma unroll
            for (int mt = 0; mt < 4; mt++)
#pragma unroll
                for (int nt = 0; nt < 4; nt++) {
                    const int r = brow + wm + mt * 16 + g;
                    const int c = bcol + wn + nt * 8 + 2 * t;
                    *(float2*)&Cf[(size_t)r * C_ + c] =
                        make_float2(acc[mt][nt][0], acc[mt][nt][1]);
                    *(float2*)&Cf[(size_t)(r + 8) * C_ + c] =
                        make_float2(acc[mt][nt][2], acc[mt][nt][3]);
                }
        } else if (bcol < 2048) {
            const float sc = (bcol < 1024) ? QSCALE : 1.0f;
            __half* qk = (__half*)Cout;
#pragma unroll
            for (int mt = 0; mt < 4; mt++)
#pragma unroll
                for (int nt = 0; nt < 4; nt++) {
                    const int r = brow + wm + mt * 16 + g;
                    const int c = bcol + wn + nt * 8 + 2 * t;
                    *(uint32_t*)&qk[(size_t)r * 2048 + c] =
                        h2u(__floats2half2_rn(acc[mt][nt][0] * sc, acc[mt][nt][1] * sc));
                    *(uint32_t*)&qk[(size_t)(r + 8) * 2048 + c] =
                        h2u(__floats2half2_rn(acc[mt][nt][2] * sc, acc[mt][nt][3] * sc));
                }
        } else {
#pragma unroll
            for (int mt = 0; mt < 4; mt++)
#pragma unroll
                for (int nt = 0; nt < 4; nt++) {
                    const int r = brow + wm + mt * 16 + g;
                    const int c = bcol + wn + nt * 8 + 2 * t;
                    const int b = r >> 11, tok = r & 2047;
                    const int cgv = c - 2048;
                    const int bh = b * 16 + (cgv >> 6), d = cgv & 63;
                    const size_t vb = ((size_t)(bh * 64 + d)) * T_ + tok;
                    g_vt[vb]            = __float2half_rn(acc[mt][nt][0]);
                    g_vt[vb + T_]       = __float2half_rn(acc[mt][nt][1]);
                    g_vt[vb + 8]        = __float2half_rn(acc[mt][nt][2]);
                    g_vt[vb + T_ + 8]   = __float2half_rn(acc[mt][nt][3]);
                }
        }
        // all warps must finish reading this tile's stages before the next
        // tile's prologue overwrites them
        __syncthreads();
    }
}

// ---------------------------------------------------------------------------
// fp16 flash attention v2 (round-15 proven) with LPT scheduling:
// heaviest q-tiles (largest qt) launch FIRST (qt = gridDim.x-1-blockIdx.x).
// ---------------------------------------------------------------------------
constexpr int FSTR = 72;                          // smem row stride (halves)
constexpr int FAQ = 0;                            // Qs: 128 x 72
constexpr int FAK = 128 * FSTR;                   // Ks: 2 x 64 x 72
constexpr int FAV = FAK + 2 * 64 * FSTR;          // Vts: 2 x 64 x 72
constexpr int FA_SMEM = (FAV + 2 * 64 * FSTR) * 2;  // 55296 bytes

__global__ __launch_bounds__(256, 2)
void flash_h_kernel(const __half* __restrict__ qkh, __half* __restrict__ y) {
    extern __shared__ __half fsm[];
    __half* Qs = fsm + FAQ;
    const uint32_t smem_base = smem_u32(fsm);

    const int qt = (int)gridDim.x - 1 - (int)blockIdx.x;   // LPT: big tiles first
    const int h = blockIdx.y, b = blockIdx.z;
    const int tid = threadIdx.x, w = tid >> 5, lane = tid & 31;
    const int g = lane >> 2, t = lane & 3;
    const int lrow = lane & 7, lmat = lane >> 3;
    const int q0 = qt * 128;
    const int wr = w * 16;

    const uint32_t aoffF = (uint32_t)(((((lmat & 1) * 8) + lrow) * FSTR + (lmat >> 1) * 8) * 2);
    const uint32_t boffF = (uint32_t)(((((lmat >> 1) * 8) + lrow) * FSTR + (lmat & 1) * 8) * 2);

    // ---- load Q tile (pre-scaled by log2e/8) ----
    {
        const __half* qbase = qkh + (size_t)(b * T_ + q0) * 2048 + h * HD_;
        for (int i = tid; i < 128 * 8; i += 256) {
            const int r = i >> 3, c = (i & 7) * 8;
            *(uint4*)&Qs[r * FSTR + c] = *(const uint4*)&qbase[(size_t)r * 2048 + c];
        }
    }
    __syncthreads();

    // ---- hoist Q fragments via ldmatrix ----
    uint32_t qf[4][4];
#pragma unroll
    for (int kk = 0; kk < 4; kk++)
        LDSM_X4(qf[kk][0], qf[kk][1], qf[kk][2], qf[kk][3],
                smem_base + (uint32_t)(wr * (FSTR * 2)) + kk * 32 + aoffF);

    float o[8][4];
#pragma unroll
    for (int nt = 0; nt < 8; nt++)
#pragma unroll
        for (int c = 0; c < 4; c++) o[nt][c] = 0.f;
    float l0 = 0.f, l1 = 0.f;

    auto issueKV = [&](int kt, int buf) {
        const int k0 = kt * 64;
        const uint32_t kbase = smem_base + (FAK + buf * 64 * FSTR) * 2;
        const uint32_t vbase = smem_base + (FAV + buf * 64 * FSTR) * 2;
        const __half* ksrc = qkh + (size_t)(b * T_ + k0) * 2048 + C_ + h * HD_;
        const __half* vsrc = g_vt + (size_t)(b * 16 + h) * HD_ * T_ + k0;
#pragma unroll
        for (int j = 0; j < 4; j++) {
            const int i = tid + j * 256;
            if (i < 512) {
                const int r = i >> 3, c = (i & 7) * 16;
                CP_ASYNC16(kbase + r * (FSTR * 2) + c, (const char*)ksrc + (size_t)r * 4096 + c);
            } else {
                const int i2 = i - 512;
                const int d = i2 >> 3, c = (i2 & 7) * 16;
                CP_ASYNC16(vbase + d * (FSTR * 2) + c, (const char*)vsrc + (size_t)d * (T_ * 2) + c);
            }
        }
    };

    const int nkt = 2 * qt + 2;
    issueKV(0, 0);
    CP_COMMIT();

    for (int kt = 0; kt < nkt; kt++) {
        const int buf = kt & 1;
        CP_WAIT0();
        __syncthreads();
        if (kt + 1 < nkt) { issueKV(kt + 1, buf ^ 1); CP_COMMIT(); }

        const uint32_t kd_u = smem_base + (FAK + buf * 64 * FSTR) * 2;
        const uint32_t vd_u = smem_base + (FAV + buf * 64 * FSTR) * 2;

        // ---- S = Q K^T (log2 domain) ----
        float s[8][4];
#pragma unroll
        for (int nt = 0; nt < 8; nt++)
#pragma unroll
            for (int c = 0; c < 4; c++) s[nt][c] = 0.f;

#pragma unroll
        for (int kk = 0; kk < 4; kk++) {
            uint32_t bfr[8][2];
#pragma unroll
            for (int np = 0; np < 4; np++)
                LDSM_X4(bfr[2 * np][0], bfr[2 * np][1], bfr[2 * np + 1][0], bfr[2 * np + 1][1],
                        kd_u + (uint32_t)(np * 16 * (FSTR * 2)) + kk * 32 + boffF);
#pragma unroll
            for (int nt = 0; nt < 8; nt++)
                mma_f16(s[nt], qf[kk], bfr[nt]);
        }

        // ---- causal mask (partial only on last two tiles) ----
        if (kt >= 2 * qt) {
            const int row0 = q0 + wr + g, row1 = row0 + 8;
            const int cb = kt * 64 + 2 * t;
#pragma unroll
            for (int nt = 0; nt < 8; nt++) {
                const int c0 = cb + nt * 8, c1 = c0 + 1;
                if (c0 > row0) s[nt][0] = -1e30f;
                if (c1 > row0) s[nt][1] = -1e30f;
                if (c0 > row1) s[nt][2] = -1e30f;
                if (c1 > row1) s[nt][3] = -1e30f;
            }
        }

        // ---- p = 2^s ; accumulate l ; pack P fragments from registers ----
        uint32_t pa[4][4];
#pragma unroll
        for (int nt = 0; nt < 8; nt++) {
            s[nt][0] = ex2f(s[nt][0]);
            s[nt][1] = ex2f(s[nt][1]);
            s[nt][2] = ex2f(s[nt][2]);
            s[nt][3] = ex2f(s[nt][3]);
            l0 += s[nt][0] + s[nt][1];
            l1 += s[nt][2] + s[nt][3];
        }
#pragma unroll
        for (int kk = 0; kk < 4; kk++) {
            pa[kk][0] = h2u(__floats2half2_rn(s[2 * kk][0],     s[2 * kk][1]));
            pa[kk][1] = h2u(__floats2half2_rn(s[2 * kk][2],     s[2 * kk][3]));
            pa[kk][2] = h2u(__floats2half2_rn(s[2 * kk + 1][0], s[2 * kk + 1][1]));
            pa[kk][3] = h2u(__floats2half2_rn(s[2 * kk + 1][2], s[2 * kk + 1][3]));
        }

        // ---- O += P V  (V^T B-fragments via ldmatrix) ----
#pragma unroll
        for (int kk = 0; kk < 4; kk++) {
            uint32_t bfr[8][2];
#pragma unroll
            for (int np = 0; np < 4; np++)
                LDSM_X4(bfr[2 * np][0], bfr[2 * np][1], bfr[2 * np + 1][0], bfr[2 * np + 1][1],
                        vd_u + (uint32_t)(np * 16 * (FSTR * 2)) + kk * 32 + boffF);
#pragma unroll
            for (int nt = 0; nt < 8; nt++)
                mma_f16(o[nt], pa[kk], bfr[nt]);
        }
    }

    // ---- epilogue: reduce l over quad lanes, normalize, store half ----
    l0 += __shfl_xor_sync(0xffffffffu, l0, 1);
    l0 += __shfl_xor_sync(0xffffffffu, l0, 2);
    l1 += __shfl_xor_sync(0xffffffffu, l1, 1);
    l1 += __shfl_xor_sync(0xffffffffu, l1, 2);
    const float inv0 = 1.f / l0, inv1 = 1.f / l1;
    __half* yb = y + (size_t)(b * T_ + q0 + wr) * C_ + h * HD_;
#pragma unroll
    for (int nt = 0; nt < 8; nt++) {
        *(uint32_t*)(yb + (size_t)g * C_ + nt * 8 + 2 * t) =
            h2u(__floats2half2_rn(o[nt][0] * inv0, o[nt][1] * inv0));
        *(uint32_t*)(yb + (size_t)(g + 8) * C_ + nt * 8 + 2 * t) =
            h2u(__floats2half2_rn(o[nt][2] * inv1, o[nt][3] * inv1));
    }
}

// ---------------------------------------------------------------------------
// kernel_launch (graph-capturable: kernel launches only)
// ---------------------------------------------------------------------------
extern "C" void kernel_launch(void* const* d_in, const int* in_sizes, int n_in,
                              void* d_out, int out_size) {
    const float* x      = (const float*)d_in[0];
    const float* w_attn = (const float*)d_in[1];
    const float* w_proj = (const float*)d_in[2];
    float* out = (float*)d_out;

    __half *xh, *wah, *wph, *qkh, *yh;
    cudaGetSymbolAddress((void**)&xh, g_xh);
    cudaGetSymbolAddress((void**)&wah, g_wah);
    cudaGetSymbolAddress((void**)&wph, g_wph);
    cudaGetSymbolAddress((void**)&qkh, g_qkh);
    cudaGetSymbolAddress((void**)&yh, g_yh);

    cudaFuncSetAttribute((const void*)hgemm<1, 24, 1536>,
                         cudaFuncAttributeMaxDynamicSharedMemorySize, HG_SMEM);
    cudaFuncSetAttribute((const void*)hgemm<0, 8, 512>,
                         cudaFuncAttributeMaxDynamicSharedMemorySize, HG_SMEM);
    cudaFuncSetAttribute(flash_h_kernel,
                         cudaFuncAttributeMaxDynamicSharedMemorySize, FA_SMEM);

    // 1. convert inputs to fp16 (x as-is; weights transposed to [N][K])
    cvt_f2h_kernel<<<(M_ * C_ / 4 + 255) / 256, 256>>>(x, xh, M_ * C_ / 4);
    transpose_f2h_kernel<<<dim3(3 * C_ / 32, C_ / 32), dim3(32, 8)>>>(w_attn, wah, C_, 3 * C_);
    transpose_f2h_kernel<<<dim3(C_ / 32, C_ / 32), dim3(32, 8)>>>(w_proj, wph, C_, C_);

    // 2. qkv = x @ w_attn  (persistent fp16 mma; Q scaled + K -> qkh, V -> vt)
    hgemm<1, 24, 1536><<<PGRID, 256, HG_SMEM>>>(xh, wah, qkh);

    // 3. fp16 flash attention v2 (LPT order) -> yh
    flash_h_kernel<<<dim3(T_ / 128, H_, B_), 256, FA_SMEM>>>(qkh, yh);

    // 4. out = y @ w_proj  (persistent, fp32 output)
    hgemm<0, 8, 512><<<PGRID, 256, HG_SMEM>>>(yh, wph, out);
}